// round 15
// baseline (speedup 1.0000x reference)
#include <cuda_runtime.h>
#include <math.h>

// ---- problem constants ----
#define NC 32
#define NBLK 128          // 128 blocks, 2 subtrees each, all co-resident
#define NTHR 1024

// ---- shared-memory float offsets ----
#define O_ASC   0         // AS  [i*132 + (l*32+j)]  (c2-order, both sweeps)
#define O_ASW   4224      // ASW [i*132 + (l*32+j)]
#define O_SMB   8448      // smB  [m*33 + c]
#define O_LGB   12672     // logB [m*36 + c]   (float4-aligned rows)
#define O_SPI   17280     // smPi [l*32 + c]
#define O_LPI   17408     // logPi[l*32 + c]
#define O_SBB   17536     // subtree beta : 2 x 84 rows x 32
#define O_SBT   22912     // subtree tbeta: 2 x 21 rows x 32
#define O_SBE   24256     // subtree eps  : 2 x 20 rows x 32
#define O_TPB   25536     // top beta : nodes 0..84
#define O_TPT   28256     // top tbeta: nodes 0..84
#define O_TPE   30976     // top eps  : nodes 0..340
#define TABF    41888
#define SMEM_BYTES (TABF * 4)   // ~164 KB -> 1 block/SM

// ---- device scratch (cross-block data: only L4 betas) ----
__device__ float  g_beta [256 * NC];   // level-4 node s -> row s
__device__ double g_ll;
__device__ unsigned int g_bar_count = 0;
__device__ unsigned int g_bar_gen   = 0;
__device__ unsigned int g_done      = 0;

__device__ __forceinline__ float wsum(float v) {
    #pragma unroll
    for (int o = 16; o; o >>= 1) v += __shfl_xor_sync(0xffffffffu, v, o);
    return v;
}
__device__ __forceinline__ float wmax(float v) {
    #pragma unroll
    for (int o = 16; o; o >>= 1) v = fmaxf(v, __shfl_xor_sync(0xffffffffu, v, o));
    return v;
}

__device__ __forceinline__ void grid_sync() {
    __syncthreads();
    if (threadIdx.x == 0) {
        __threadfence();
        volatile unsigned int* vg = &g_bar_gen;
        unsigned int old = *vg;
        if (atomicAdd(&g_bar_count, 1u) == NBLK - 1u) {
            atomicExch(&g_bar_count, 0u);
            __threadfence();
            atomicAdd(&g_bar_gen, 1u);
        } else {
            while (*vg == old) __nanosleep(32);
        }
        __threadfence();
    }
    __syncthreads();
}

// ---------------------------------------------------------------------------
// up matvec: lane = state i.  tb[i] = sum_c2 AS[i][c2] * st[c2]
// st4 = 128 consecutive floats = 4 child beta rows in c2-order (smem or gmem)
// ---------------------------------------------------------------------------
__device__ __forceinline__ float up_matvec(const float4* __restrict__ ASc4,
                                           const float4* __restrict__ st4, int lane) {
    const float4* arow = ASc4 + lane * 33;
    float a0 = 0.f, a1 = 0.f, a2 = 0.f, a3 = 0.f;
    #pragma unroll
    for (int k = 0; k < 32; k++) {
        float4 a = arow[k];
        float4 b = st4[k];
        a0 = fmaf(a.x, b.x, a0); a1 = fmaf(a.y, b.y, a1);
        a2 = fmaf(a.z, b.z, a2); a3 = fmaf(a.w, b.w, a3);
    }
    return (a0 + a1) + (a2 + a3);
}

__device__ __forceinline__ void up_epi(float tb, int lab, const float* __restrict__ smBt,
        float* __restrict__ tbeta_row, float* __restrict__ beta_row, int lane) {
    tbeta_row[lane] = tb;
    float bl = tb * smBt[lab * 33 + lane];
    beta_row[lane] = bl / wsum(bl);
}

// ---------------------------------------------------------------------------
// down matvec: r per-lane (lane = i).  s/w quads over c2 = 4*lane..4*lane+3
// ---------------------------------------------------------------------------
__device__ __forceinline__ void down_matvec(float r,
        const float4* __restrict__ ASc4, const float4* __restrict__ ASW4,
        int lane, float4& s4, float4& w4) {
    s4 = make_float4(0.f, 0.f, 0.f, 0.f);
    w4 = make_float4(0.f, 0.f, 0.f, 0.f);
    #pragma unroll
    for (int i = 0; i < NC; i++) {
        float ri = __shfl_sync(0xffffffffu, r, i);
        float4 a = ASc4[i * 33 + lane];
        float4 w = ASW4[i * 33 + lane];
        s4.x = fmaf(a.x, ri, s4.x); s4.y = fmaf(a.y, ri, s4.y);
        s4.z = fmaf(a.z, ri, s4.z); s4.w = fmaf(a.w, ri, s4.w);
        w4.x = fmaf(w.x, ri, w4.x); w4.y = fmaf(w.y, ri, w4.y);
        w4.z = fmaf(w.z, ri, w4.z); w4.w = fmaf(w.w, ri, w4.w);
    }
}

// down epilogue: cbeta = base of child0's 32-float row (children contiguous);
// ceps (nullable) same layout; clab4 = labels + first_child.
__device__ __forceinline__ void down_epi(const float* __restrict__ cbeta,
        float* __restrict__ ceps, const int* __restrict__ clab4,
        const float* __restrict__ logBt, const float* __restrict__ logPit,
        float4 s4, float4 w4, int lane, float& acc) {
    const int l = lane >> 3, jb = (lane * 4) & 31;
    const float4 b = *(const float4*)(cbeta + l * 32 + jb);
    float4 ev = make_float4(s4.x * b.x, s4.y * b.y, s4.z * b.z, s4.w * b.w);
    if (ceps) *(float4*)(ceps + l * 32 + jb) = ev;
    const int lb = clab4[l];
    const float4 g = *(const float4*)(logBt + lb * 36 + jb);
    acc += b.x * w4.x + b.y * w4.y + b.z * w4.z + b.w * w4.w
         + ev.x * g.x + ev.y * g.y + ev.z * g.z + ev.w * g.w;
    if (logPit) {
        const float4 p = *(const float4*)(logPit + l * 32 + jb);
        acc += ev.x * p.x + ev.y * p.y + ev.z * p.z + ev.w * p.w;
    }
}

// ---------------------------------------------------------------------------
// the single fused kernel — ONE grid barrier
// ---------------------------------------------------------------------------
__global__ void __launch_bounds__(NTHR, 1) fused_kernel(
        const int* __restrict__ labels, const float* __restrict__ A,
        const float* __restrict__ B, const float* __restrict__ Pi,
        const float* __restrict__ SP, float* __restrict__ out)
{
    extern __shared__ float sh[];
    __shared__ double blk_ll;
    const int tid  = threadIdx.x;
    const int lane = tid & 31;
    const int w    = tid >> 5;                 // warp in block (0..31)
    const int bid  = blockIdx.x;

    if (tid == 0) blk_ll = 0.0;
    if (bid == 0 && tid == 0) g_ll = 0.0;

    // ---- table build (per block, redundant) ----
    {
        float sp[4], lsp[4], smsp[4];
        #pragma unroll
        for (int l = 0; l < 4; l++) sp[l] = SP[l];
        float mx = fmaxf(fmaxf(sp[0], sp[1]), fmaxf(sp[2], sp[3]));
        float ssum = 0.f;
        #pragma unroll
        for (int l = 0; l < 4; l++) ssum += expf(sp[l] - mx);
        float lse = logf(ssum) + mx;
        #pragma unroll
        for (int l = 0; l < 4; l++) { lsp[l] = sp[l] - lse; smsp[l] = expf(lsp[l]); }

        // A softmax over i (=lane); warp w -> cols 4w..4w+3 (col = j*4+l)
        float av[4];
        #pragma unroll
        for (int cc = 0; cc < 4; cc++) av[cc] = A[lane * 128 + w * 4 + cc];
        #pragma unroll
        for (int cc = 0; cc < 4; cc++) {
            const int col = w * 4 + cc, j = col >> 2, l = col & 3;
            float a = av[cc];
            float m = wmax(a);
            float e = expf(a - m);
            float s = wsum(e);
            float lsm = a - m - logf(s);
            float as  = (e / s) * smsp[l];
            sh[O_ASC + lane * 132 + (l * 32 + j)] = as;
            sh[O_ASW + lane * 132 + (l * 32 + j)] = as * (lsm + lsp[l]);
        }
        // B softmax over m; warp w -> row c=w
        {
            const int c = w;
            float v[4];
            #pragma unroll
            for (int k = 0; k < 4; k++) v[k] = B[c * 128 + lane + 32 * k];
            float m = fmaxf(fmaxf(v[0], v[1]), fmaxf(v[2], v[3]));
            m = wmax(m);
            float s = 0.f;
            #pragma unroll
            for (int k = 0; k < 4; k++) s += expf(v[k] - m);
            s = wsum(s);
            float l2 = logf(s) + m;
            #pragma unroll
            for (int k = 0; k < 4; k++) {
                const int mm = lane + 32 * k;
                float lsm = v[k] - l2;
                sh[O_SMB + mm * 33 + c] = expf(lsm);
                sh[O_LGB + mm * 36 + c] = lsm;
            }
        }
        // Pi softmax over c (=lane); warps 0..3 -> column l
        if (w < 4) {
            float pv = Pi[lane * 4 + w];
            float m = wmax(pv);
            float e = expf(pv - m);
            float s = wsum(e);
            float lsm = pv - m - logf(s);
            sh[O_SPI + w * 32 + lane] = e / s;
            sh[O_LPI + w * 32 + lane] = lsm;
        }
    }
    __syncthreads();

    const float4* ASc4 = (const float4*)(sh + O_ASC);
    const float4* ASW4 = (const float4*)(sh + O_ASW);
    const float*  smBt = sh + O_SMB;
    const float*  lgBt = sh + O_LGB;
    const float*  sPit = sh + O_SPI;
    const float*  lPit = sh + O_LPI;

    float* sbB0 = sh + O_SBB;   // [t*84 + row]*32; rows: L5 q->q, L6 k->4+k, leaf e->20+e
    float* sbT0 = sh + O_SBT;   // rows: root 0, L5 1+q, L6 5+k
    float* sbE0 = sh + O_SBE;   // rows: L5 q, L6 4+k
    float* topB = sh + O_TPB;   // nodes 0..84
    float* topT = sh + O_TPT;   // nodes 0..84
    float* topE = sh + O_TPE;   // nodes 0..340

    // =========== P1: subtree up-sweep (in-block) ===========
    {   // L6 parents (+ leaf betas): warp -> (t = w>>4, k = w&15)
        const int t = w >> 4, k = w & 15;
        const int s = 2 * bid + t;
        const int h = 1365 + 16 * s + k;
        const int lf = 5461 + 64 * s + 4 * k;
        float* sbB = sbB0 + t * 84 * 32;
        #pragma unroll
        for (int l = 0; l < 4; l++) {
            const int lab = labels[lf + l];
            float v = sPit[l * 32 + lane] * smBt[lab * 33 + lane];
            v = v / wsum(v);
            sbB[(20 + 4 * k + l) * 32 + lane] = v;
        }
        __syncwarp();
        float tb = up_matvec(ASc4, (const float4*)(sbB + (20 + 4 * k) * 32), lane);
        up_epi(tb, labels[h], smBt, sbT0 + (t * 21 + 5 + k) * 32,
               sbB + (4 + k) * 32, lane);
    }
    __syncthreads();
    if (w < 8) {   // L5 parents: (t = w>>2, q = w&3)
        const int t = w >> 2, q = w & 3;
        const int s = 2 * bid + t;
        float* sbB = sbB0 + t * 84 * 32;
        float tb = up_matvec(ASc4, (const float4*)(sbB + (4 + 4 * q) * 32), lane);
        up_epi(tb, labels[341 + 4 * s + q], smBt, sbT0 + (t * 21 + 1 + q) * 32,
               sbB + q * 32, lane);
    }
    __syncthreads();
    if (w < 2) {   // L4 roots -> publish beta GLOBALLY
        const int t = w, s = 2 * bid + t;
        float* sbB = sbB0 + t * 84 * 32;
        float tb = up_matvec(ASc4, (const float4*)sbB, lane);
        up_epi(tb, labels[85 + s], smBt, sbT0 + (t * 21) * 32,
               g_beta + s * 32, lane);
    }
    grid_sync();                                            // THE barrier

    // =========== P2: redundant top (levels 0..3 up + down), all in-block ===
    float acc = 0.f, acc_top = 0.f;
    #pragma unroll
    for (int rep = 0; rep < 2; rep++) {        // up L3: 64 parents, 2/warp
        const int p = w + rep * 32, node = 21 + p;
        float tb = up_matvec(ASc4, (const float4*)(g_beta + 4 * p * 32), lane);
        up_epi(tb, labels[node], smBt, topT + node * 32, topB + node * 32, lane);
    }
    __syncthreads();
    if (w < 16) {  // up L2
        const int node = 5 + w;
        float tb = up_matvec(ASc4, (const float4*)(topB + (21 + 4 * w) * 32), lane);
        up_epi(tb, labels[node], smBt, topT + node * 32, topB + node * 32, lane);
    }
    __syncthreads();
    if (w < 4) {   // up L1
        const int node = 1 + w;
        float tb = up_matvec(ASc4, (const float4*)(topB + (5 + 4 * w) * 32), lane);
        up_epi(tb, labels[node], smBt, topT + node * 32, topB + node * 32, lane);
    }
    __syncthreads();
    if (w == 0) {  // up L0
        float tb = up_matvec(ASc4, (const float4*)(topB + 1 * 32), lane);
        up_epi(tb, labels[0], smBt, topT, topB, lane);
    }
    __syncthreads();
    if (w == 0) {  // down L0: eps_root = beta_root
        float r = topB[lane] / topT[lane];
        float4 s4, w4;
        down_matvec(r, ASc4, ASW4, lane, s4, w4);
        down_epi(topB + 32, topE + 32, labels + 1, lgBt, 0, s4, w4, lane, acc_top);
        acc_top += topB[lane] * lgBt[labels[0] * 36 + lane];
        topE[lane] = topB[lane];
    }
    __syncthreads();
    if (w < 4) {   // down L1
        const int node = 1 + w;
        float r = topE[node * 32 + lane] / topT[node * 32 + lane];
        float4 s4, w4;
        down_matvec(r, ASc4, ASW4, lane, s4, w4);
        down_epi(topB + (5 + 4 * w) * 32, topE + (5 + 4 * w) * 32,
                 labels + 5 + 4 * w, lgBt, 0, s4, w4, lane, acc_top);
    }
    __syncthreads();
    if (w < 16) {  // down L2 -> eps L3
        const int node = 5 + w;
        float r = topE[node * 32 + lane] / topT[node * 32 + lane];
        float4 s4, w4;
        down_matvec(r, ASc4, ASW4, lane, s4, w4);
        down_epi(topB + (21 + 4 * w) * 32, topE + (21 + 4 * w) * 32,
                 labels + 21 + 4 * w, lgBt, 0, s4, w4, lane, acc_top);
    }
    __syncthreads();
    #pragma unroll
    for (int rep = 0; rep < 2; rep++) {        // down L3 -> eps L4 (local)
        const int p = w + rep * 32, node = 21 + p;
        float r = topE[node * 32 + lane] / topT[node * 32 + lane];
        float4 s4, w4;
        down_matvec(r, ASc4, ASW4, lane, s4, w4);
        down_epi(g_beta + 4 * p * 32, topE + (85 + 4 * p) * 32,
                 labels + 85 + 4 * p, lgBt, 0, s4, w4, lane, acc_top);
    }
    __syncthreads();
    if (bid == 0) acc += acc_top;              // top ll counted once

    // =========== P3: subtree down-sweep (in-block) ===========
    if (w < 2) {   // L4 roots
        const int t = w, s = 2 * bid + t;
        float r = topE[(85 + s) * 32 + lane] / sbT0[(t * 21) * 32 + lane];
        float4 s4, w4;
        down_matvec(r, ASc4, ASW4, lane, s4, w4);
        down_epi(sbB0 + t * 84 * 32, sbE0 + t * 20 * 32,
                 labels + 341 + 4 * s, lgBt, 0, s4, w4, lane, acc);
    }
    __syncthreads();
    if (w < 8) {   // L5 parents
        const int t = w >> 2, q = w & 3;
        const int s = 2 * bid + t;
        float* sbB = sbB0 + t * 84 * 32;
        float* sbE = sbE0 + t * 20 * 32;
        float r = sbE[q * 32 + lane] / sbT0[(t * 21 + 1 + q) * 32 + lane];
        float4 s4, w4;
        down_matvec(r, ASc4, ASW4, lane, s4, w4);
        down_epi(sbB + (4 + 4 * q) * 32, sbE + (4 + 4 * q) * 32,
                 labels + 1365 + 16 * s + 4 * q, lgBt, 0, s4, w4, lane, acc);
    }
    __syncthreads();
    {              // L6 parents (leaf children, ll only)
        const int t = w >> 4, k = w & 15;
        const int s = 2 * bid + t;
        float* sbB = sbB0 + t * 84 * 32;
        float* sbE = sbE0 + t * 20 * 32;
        float r = sbE[(4 + k) * 32 + lane] / sbT0[(t * 21 + 5 + k) * 32 + lane];
        float4 s4, w4;
        down_matvec(r, ASc4, ASW4, lane, s4, w4);
        down_epi(sbB + (20 + 4 * k) * 32, 0, labels + 5461 + 64 * s + 4 * k,
                 lgBt, lPit, s4, w4, lane, acc);
    }

    // ---- final reduction: last block writes the output ----
    acc = wsum(acc);
    if (lane == 0) atomicAdd(&blk_ll, (double)acc);
    __syncthreads();
    if (tid == 0) {
        atomicAdd(&g_ll, blk_ll);
        __threadfence();
        if (atomicAdd(&g_done, 1u) == NBLK - 1u) {
            __threadfence();
            double v = *((volatile double*)&g_ll);
            out[0] = (float)v;
            g_done = 0;
            __threadfence();
        }
    }
}

extern "C" void kernel_launch(void* const* d_in, const int* in_sizes, int n_in,
                              void* d_out, int out_size) {
    const int*   labels = (const int*)  d_in[0];
    const float* A      = (const float*)d_in[1];
    const float* B      = (const float*)d_in[2];
    const float* Pi     = (const float*)d_in[3];
    const float* SP     = (const float*)d_in[4];

    static int smem_set = 0;
    if (!smem_set) {
        cudaFuncSetAttribute(fused_kernel,
                             cudaFuncAttributeMaxDynamicSharedMemorySize, SMEM_BYTES);
        smem_set = 1;
    }
    fused_kernel<<<NBLK, NTHR, SMEM_BYTES>>>(labels, A, B, Pi, SP, (float*)d_out);
}

// round 17
// speedup vs baseline: 2.0054x; 2.0054x over previous
#include <cuda_runtime.h>
#include <math.h>

// ---- problem constants ----
#define NC 32
#define NBLK 128          // 128 blocks, 2 subtrees each, all co-resident
#define NTHR 1024

// ---- shared-memory float offsets ----
#define O_ASC   0         // AS  [i*132 + (l*32+j)]  (c2-order, both sweeps)
#define O_ASW   4224      // ASW [i*132 + (l*32+j)]
#define O_SMB   8448      // smB  [m*33 + c]
#define O_LGB   12672     // logB [m*36 + c]   (float4-aligned rows)
#define O_SPI   17280     // smPi [l*32 + c]
#define O_LPI   17408     // logPi[l*32 + c]
#define O_SBB   17536     // subtree beta : 2 x 84 rows x 32
#define O_SBT   22912     // subtree tbeta: 2 x 21 rows x 32
#define O_SBE   24256     // subtree eps  : 2 x 20 rows x 32
#define O_TPB   25536     // top beta : nodes 0..84
#define O_TPT   28256     // top tbeta: nodes 0..84
#define O_TPE   30976     // top eps  : nodes 0..84 ONLY
#define O_TPE4  33696     // eps of own L3 parent's 4 children (L4)
#define TABF    33824
#define SMEM_BYTES (TABF * 4)   // ~132 KB -> 1 block/SM, L1 carveout ~96 KB

// ---- device scratch (cross-block data: only L4 betas) ----
__device__ float  g_beta [256 * NC];   // level-4 node s -> row s
__device__ double g_ll;
__device__ unsigned int g_bar_count = 0;
__device__ unsigned int g_bar_gen   = 0;
__device__ unsigned int g_done      = 0;

__device__ __forceinline__ float wsum(float v) {
    #pragma unroll
    for (int o = 16; o; o >>= 1) v += __shfl_xor_sync(0xffffffffu, v, o);
    return v;
}
__device__ __forceinline__ float wmax(float v) {
    #pragma unroll
    for (int o = 16; o; o >>= 1) v = fmaxf(v, __shfl_xor_sync(0xffffffffu, v, o));
    return v;
}

__device__ __forceinline__ void grid_sync() {
    __syncthreads();
    if (threadIdx.x == 0) {
        __threadfence();
        volatile unsigned int* vg = &g_bar_gen;
        unsigned int old = *vg;
        if (atomicAdd(&g_bar_count, 1u) == NBLK - 1u) {
            atomicExch(&g_bar_count, 0u);
            __threadfence();
            atomicAdd(&g_bar_gen, 1u);
        } else {
            while (*vg == old) __nanosleep(32);
        }
        __threadfence();
    }
    __syncthreads();
}

// ---------------------------------------------------------------------------
// up matvec: lane = state i.  tb[i] = sum_c2 AS[i][c2] * st[c2]
// partial unroll (8) keeps register pressure under the 64-reg cap.
// ---------------------------------------------------------------------------
__device__ __forceinline__ float up_matvec(const float4* __restrict__ ASc4,
                                           const float4* __restrict__ st4, int lane) {
    const float4* arow = ASc4 + lane * 33;
    float a0 = 0.f, a1 = 0.f, a2 = 0.f, a3 = 0.f;
    #pragma unroll 8
    for (int k = 0; k < 32; k++) {
        float4 a = arow[k];
        float4 b = st4[k];
        a0 = fmaf(a.x, b.x, a0); a1 = fmaf(a.y, b.y, a1);
        a2 = fmaf(a.z, b.z, a2); a3 = fmaf(a.w, b.w, a3);
    }
    return (a0 + a1) + (a2 + a3);
}

__device__ __forceinline__ void up_epi(float tb, int lab, const float* __restrict__ smBt,
        float* __restrict__ tbeta_row, float* __restrict__ beta_row, int lane) {
    tbeta_row[lane] = tb;
    float bl = tb * smBt[lab * 33 + lane];
    beta_row[lane] = bl / wsum(bl);
}

// ---------------------------------------------------------------------------
// down matvec: r per-lane (lane = i).  s/w quads over c2 = 4*lane..4*lane+3
// ---------------------------------------------------------------------------
__device__ __forceinline__ void down_matvec(float r,
        const float4* __restrict__ ASc4, const float4* __restrict__ ASW4,
        int lane, float4& s4, float4& w4) {
    s4 = make_float4(0.f, 0.f, 0.f, 0.f);
    w4 = make_float4(0.f, 0.f, 0.f, 0.f);
    #pragma unroll 8
    for (int i = 0; i < NC; i++) {
        float ri = __shfl_sync(0xffffffffu, r, i);
        float4 a = ASc4[i * 33 + lane];
        float4 w = ASW4[i * 33 + lane];
        s4.x = fmaf(a.x, ri, s4.x); s4.y = fmaf(a.y, ri, s4.y);
        s4.z = fmaf(a.z, ri, s4.z); s4.w = fmaf(a.w, ri, s4.w);
        w4.x = fmaf(w.x, ri, w4.x); w4.y = fmaf(w.y, ri, w4.y);
        w4.z = fmaf(w.z, ri, w4.z); w4.w = fmaf(w.w, ri, w4.w);
    }
}

// down epilogue: cbeta = base of child0's 32-float row (children contiguous);
// ceps (nullable) same layout; clab4 = labels + first_child.
__device__ __forceinline__ void down_epi(const float* __restrict__ cbeta,
        float* __restrict__ ceps, const int* __restrict__ clab4,
        const float* __restrict__ logBt, const float* __restrict__ logPit,
        float4 s4, float4 w4, int lane, float& acc) {
    const int l = lane >> 3, jb = (lane * 4) & 31;
    const float4 b = *(const float4*)(cbeta + l * 32 + jb);
    float4 ev = make_float4(s4.x * b.x, s4.y * b.y, s4.z * b.z, s4.w * b.w);
    if (ceps) *(float4*)(ceps + l * 32 + jb) = ev;
    const int lb = clab4[l];
    const float4 g = *(const float4*)(logBt + lb * 36 + jb);
    acc += b.x * w4.x + b.y * w4.y + b.z * w4.z + b.w * w4.w
         + ev.x * g.x + ev.y * g.y + ev.z * g.z + ev.w * g.w;
    if (logPit) {
        const float4 p = *(const float4*)(logPit + l * 32 + jb);
        acc += ev.x * p.x + ev.y * p.y + ev.z * p.z + ev.w * p.w;
    }
}

// ---------------------------------------------------------------------------
// the single fused kernel — ONE grid barrier
// ---------------------------------------------------------------------------
__global__ void __launch_bounds__(NTHR, 1) fused_kernel(
        const int* __restrict__ labels, const float* __restrict__ A,
        const float* __restrict__ B, const float* __restrict__ Pi,
        const float* __restrict__ SP, float* __restrict__ out)
{
    extern __shared__ float sh[];
    __shared__ double blk_ll;
    const int tid  = threadIdx.x;
    const int lane = tid & 31;
    const int w    = tid >> 5;                 // warp in block (0..31)
    const int bid  = blockIdx.x;

    if (tid == 0) blk_ll = 0.0;
    if (bid == 0 && tid == 0) g_ll = 0.0;

    // ---- table build (per block, redundant) ----
    {
        float sp[4], lsp[4], smsp[4];
        #pragma unroll
        for (int l = 0; l < 4; l++) sp[l] = SP[l];
        float mx = fmaxf(fmaxf(sp[0], sp[1]), fmaxf(sp[2], sp[3]));
        float ssum = 0.f;
        #pragma unroll
        for (int l = 0; l < 4; l++) ssum += expf(sp[l] - mx);
        float lse = logf(ssum) + mx;
        #pragma unroll
        for (int l = 0; l < 4; l++) { lsp[l] = sp[l] - lse; smsp[l] = expf(lsp[l]); }

        // A softmax over i (=lane); warp w -> cols 4w..4w+3 (col = j*4+l)
        float av[4];
        #pragma unroll
        for (int cc = 0; cc < 4; cc++) av[cc] = A[lane * 128 + w * 4 + cc];
        #pragma unroll
        for (int cc = 0; cc < 4; cc++) {
            const int col = w * 4 + cc, j = col >> 2, l = col & 3;
            float a = av[cc];
            float m = wmax(a);
            float e = expf(a - m);
            float s = wsum(e);
            float lsm = a - m - logf(s);
            float as  = (e / s) * smsp[l];
            sh[O_ASC + lane * 132 + (l * 32 + j)] = as;
            sh[O_ASW + lane * 132 + (l * 32 + j)] = as * (lsm + lsp[l]);
        }
        // B softmax over m; warp w -> row c=w
        {
            const int c = w;
            float v[4];
            #pragma unroll
            for (int k = 0; k < 4; k++) v[k] = B[c * 128 + lane + 32 * k];
            float m = fmaxf(fmaxf(v[0], v[1]), fmaxf(v[2], v[3]));
            m = wmax(m);
            float s = 0.f;
            #pragma unroll
            for (int k = 0; k < 4; k++) s += expf(v[k] - m);
            s = wsum(s);
            float l2 = logf(s) + m;
            #pragma unroll
            for (int k = 0; k < 4; k++) {
                const int mm = lane + 32 * k;
                float lsm = v[k] - l2;
                sh[O_SMB + mm * 33 + c] = expf(lsm);
                sh[O_LGB + mm * 36 + c] = lsm;
            }
        }
        // Pi softmax over c (=lane); warps 0..3 -> column l
        if (w < 4) {
            float pv = Pi[lane * 4 + w];
            float m = wmax(pv);
            float e = expf(pv - m);
            float s = wsum(e);
            float lsm = pv - m - logf(s);
            sh[O_SPI + w * 32 + lane] = e / s;
            sh[O_LPI + w * 32 + lane] = lsm;
        }
    }
    __syncthreads();

    const float4* ASc4 = (const float4*)(sh + O_ASC);
    const float4* ASW4 = (const float4*)(sh + O_ASW);
    const float*  smBt = sh + O_SMB;
    const float*  lgBt = sh + O_LGB;
    const float*  sPit = sh + O_SPI;
    const float*  lPit = sh + O_LPI;

    float* sbB0 = sh + O_SBB;   // [t*84 + row]*32; rows: L5 q->q, L6 k->4+k, leaf e->20+e
    float* sbT0 = sh + O_SBT;   // rows: root 0, L5 1+q, L6 5+k
    float* sbE0 = sh + O_SBE;   // rows: L5 q, L6 4+k
    float* topB = sh + O_TPB;   // nodes 0..84
    float* topT = sh + O_TPT;   // nodes 0..84
    float* topE = sh + O_TPE;   // nodes 0..84
    float* topE4 = sh + O_TPE4; // 4 rows: eps of own L3 parent's children

    // =========== P1: subtree up-sweep (in-block) ===========
    {   // L6 parents (+ leaf betas): warp -> (t = w>>4, k = w&15)
        const int t = w >> 4, k = w & 15;
        const int s = 2 * bid + t;
        const int h = 1365 + 16 * s + k;
        const int lf = 5461 + 64 * s + 4 * k;
        float* sbB = sbB0 + t * 84 * 32;
        #pragma unroll
        for (int l = 0; l < 4; l++) {
            const int lab = labels[lf + l];
            float v = sPit[l * 32 + lane] * smBt[lab * 33 + lane];
            v = v / wsum(v);
            sbB[(20 + 4 * k + l) * 32 + lane] = v;
        }
        __syncwarp();
        float tb = up_matvec(ASc4, (const float4*)(sbB + (20 + 4 * k) * 32), lane);
        up_epi(tb, labels[h], smBt, sbT0 + (t * 21 + 5 + k) * 32,
               sbB + (4 + k) * 32, lane);
    }
    __syncthreads();
    if (w < 8) {   // L5 parents: (t = w>>2, q = w&3)
        const int t = w >> 2, q = w & 3;
        const int s = 2 * bid + t;
        float* sbB = sbB0 + t * 84 * 32;
        float tb = up_matvec(ASc4, (const float4*)(sbB + (4 + 4 * q) * 32), lane);
        up_epi(tb, labels[341 + 4 * s + q], smBt, sbT0 + (t * 21 + 1 + q) * 32,
               sbB + q * 32, lane);
    }
    __syncthreads();
    if (w < 2) {   // L4 roots -> publish beta GLOBALLY
        const int t = w, s = 2 * bid + t;
        float* sbB = sbB0 + t * 84 * 32;
        float tb = up_matvec(ASc4, (const float4*)sbB, lane);
        up_epi(tb, labels[85 + s], smBt, sbT0 + (t * 21) * 32,
               g_beta + s * 32, lane);
    }
    grid_sync();                                            // THE barrier

    // =========== P2: redundant top (levels 0..3), register-lean ===========
    float acc = 0.f, acc_top = 0.f;
    #pragma unroll 1
    for (int rep = 0; rep < 2; rep++) {        // up L3: 64 parents, 2/warp
        const int p = w + rep * 32, node = 21 + p;
        float tb = up_matvec(ASc4, (const float4*)(g_beta + 4 * p * 32), lane);
        up_epi(tb, labels[node], smBt, topT + node * 32, topB + node * 32, lane);
    }
    __syncthreads();
    if (w < 16) {  // up L2
        const int node = 5 + w;
        float tb = up_matvec(ASc4, (const float4*)(topB + (21 + 4 * w) * 32), lane);
        up_epi(tb, labels[node], smBt, topT + node * 32, topB + node * 32, lane);
    }
    __syncthreads();
    if (w < 4) {   // up L1
        const int node = 1 + w;
        float tb = up_matvec(ASc4, (const float4*)(topB + (5 + 4 * w) * 32), lane);
        up_epi(tb, labels[node], smBt, topT + node * 32, topB + node * 32, lane);
    }
    __syncthreads();
    if (w == 0) {  // up L0
        float tb = up_matvec(ASc4, (const float4*)(topB + 1 * 32), lane);
        up_epi(tb, labels[0], smBt, topT, topB, lane);
    }
    __syncthreads();
    if (w == 0) {  // down L0: eps_root = beta_root
        float r = topB[lane] / topT[lane];
        float4 s4, w4;
        down_matvec(r, ASc4, ASW4, lane, s4, w4);
        down_epi(topB + 32, topE + 32, labels + 1, lgBt, 0, s4, w4, lane, acc_top);
        acc_top += topB[lane] * lgBt[labels[0] * 36 + lane];
        topE[lane] = topB[lane];
    }
    __syncthreads();
    if (w < 4) {   // down L1
        const int node = 1 + w;
        float r = topE[node * 32 + lane] / topT[node * 32 + lane];
        float4 s4, w4;
        down_matvec(r, ASc4, ASW4, lane, s4, w4);
        down_epi(topB + (5 + 4 * w) * 32, topE + (5 + 4 * w) * 32,
                 labels + 5 + 4 * w, lgBt, 0, s4, w4, lane, acc_top);
    }
    __syncthreads();
    if (w < 16) {  // down L2 -> eps L3 (rows 21..84)
        const int node = 5 + w;
        float r = topE[node * 32 + lane] / topT[node * 32 + lane];
        float4 s4, w4;
        down_matvec(r, ASc4, ASW4, lane, s4, w4);
        down_epi(topB + (21 + 4 * w) * 32, topE + (21 + 4 * w) * 32,
                 labels + 21 + 4 * w, lgBt, 0, s4, w4, lane, acc_top);
    }
    __syncthreads();
    // down L3: ONLY own parent p_own = bid>>1 (eps for own 2 subtree roots);
    // ll term for parent p is accumulated by block 2p exactly once.
    if (w == 0) {
        const int p = bid >> 1, node = 21 + p;
        float r = topE[node * 32 + lane] / topT[node * 32 + lane];
        float4 s4, w4;
        down_matvec(r, ASc4, ASW4, lane, s4, w4);
        float accl = 0.f;
        down_epi(g_beta + 4 * p * 32, topE4, labels + 85 + 4 * p,
                 lgBt, 0, s4, w4, lane, accl);
        if ((bid & 1) == 0) acc += accl;
    }
    __syncthreads();
    if (bid == 0) acc += acc_top;              // top ll counted once

    // =========== P3: subtree down-sweep (in-block) ===========
    if (w < 2) {   // L4 roots (eps from topE4; child pos within own parent)
        const int t = w, s = 2 * bid + t;
        const int cpos = s - 4 * (bid >> 1);   // 0..3
        float r = topE4[cpos * 32 + lane] / sbT0[(t * 21) * 32 + lane];
        float4 s4, w4;
        down_matvec(r, ASc4, ASW4, lane, s4, w4);
        down_epi(sbB0 + t * 84 * 32, sbE0 + t * 20 * 32,
                 labels + 341 + 4 * s, lgBt, 0, s4, w4, lane, acc);
    }
    __syncthreads();
    if (w < 8) {   // L5 parents
        const int t = w >> 2, q = w & 3;
        const int s = 2 * bid + t;
        float* sbB = sbB0 + t * 84 * 32;
        float* sbE = sbE0 + t * 20 * 32;
        float r = sbE[q * 32 + lane] / sbT0[(t * 21 + 1 + q) * 32 + lane];
        float4 s4, w4;
        down_matvec(r, ASc4, ASW4, lane, s4, w4);
        down_epi(sbB + (4 + 4 * q) * 32, sbE + (4 + 4 * q) * 32,
                 labels + 1365 + 16 * s + 4 * q, lgBt, 0, s4, w4, lane, acc);
    }
    __syncthreads();
    {              // L6 parents (leaf children, ll only)
        const int t = w >> 4, k = w & 15;
        const int s = 2 * bid + t;
        float* sbB = sbB0 + t * 84 * 32;
        float* sbE = sbE0 + t * 20 * 32;
        float r = sbE[(4 + k) * 32 + lane] / sbT0[(t * 21 + 5 + k) * 32 + lane];
        float4 s4, w4;
        down_matvec(r, ASc4, ASW4, lane, s4, w4);
        down_epi(sbB + (20 + 4 * k) * 32, 0, labels + 5461 + 64 * s + 4 * k,
                 lgBt, lPit, s4, w4, lane, acc);
    }

    // ---- final reduction: last block writes the output ----
    acc = wsum(acc);
    if (lane == 0) atomicAdd(&blk_ll, (double)acc);
    __syncthreads();
    if (tid == 0) {
        atomicAdd(&g_ll, blk_ll);
        __threadfence();
        if (atomicAdd(&g_done, 1u) == NBLK - 1u) {
            __threadfence();
            double v = *((volatile double*)&g_ll);
            out[0] = (float)v;
            g_done = 0;
            __threadfence();
        }
    }
}

extern "C" void kernel_launch(void* const* d_in, const int* in_sizes, int n_in,
                              void* d_out, int out_size) {
    const int*   labels = (const int*)  d_in[0];
    const float* A      = (const float*)d_in[1];
    const float* B      = (const float*)d_in[2];
    const float* Pi     = (const float*)d_in[3];
    const float* SP     = (const float*)d_in[4];

    static int smem_set = 0;
    if (!smem_set) {
        cudaFuncSetAttribute(fused_kernel,
                             cudaFuncAttributeMaxDynamicSharedMemorySize, SMEM_BYTES);
        smem_set = 1;
    }
    fused_kernel<<<NBLK, NTHR, SMEM_BYTES>>>(labels, A, B, Pi, SP, (float*)d_out);
}